// round 1
// baseline (speedup 1.0000x reference)
#include <cuda_runtime.h>
#include <cstdint>

// Problem constants
#define TABLE_SIZE 524288u          // 2^19 -> modulo is a mask
#define NUM_LEVELS 16
#define N_POINTS (1u << 20)
#define HASH_PRIME 2654435761u

// scalings[l] = floor(16 * (64^(1/15))^l) computed in fp32 as the reference does.
// 64^(1/15) = 2^0.4; fl32(2^0.4) is ~+0.3ulp above exact, so l=5,10,15 land at
// 64/256/1024 (just above the integer boundary before floor).
__constant__ float kScale[NUM_LEVELS] = {
    16.0f, 21.0f, 27.0f, 36.0f, 48.0f, 64.0f, 84.0f, 111.0f,
    147.0f, 194.0f, 256.0f, 337.0f, 445.0f, 588.0f, 776.0f, 1024.0f
};

__global__ __launch_bounds__(256)
void hash_encode_kernel(const float2* __restrict__ x,
                        const float2* __restrict__ table,
                        float2* __restrict__ out)
{
    const uint32_t t = blockIdx.x * blockDim.x + threadIdx.x;   // t = p*16 + l
    if (t >= N_POINTS * NUM_LEVELS) return;

    const uint32_t p = t >> 4;
    const uint32_t l = t & 15u;

    // 16 consecutive lanes read the same point -> single L1 sector broadcast
    const float2 xp = __ldg(&x[p]);

    const float s  = kScale[l];
    const float sx = xp.x * s;
    const float sy = xp.y * s;

    const float fxf = floorf(sx);
    const float fyf = floorf(sy);
    const float cxf = ceilf(sx);
    const float cyf = ceilf(sy);

    const uint32_t fx = (uint32_t)(int32_t)fxf;
    const uint32_t fy = (uint32_t)(int32_t)fyf;
    const uint32_t cx = (uint32_t)(int32_t)cxf;
    const uint32_t cy = (uint32_t)(int32_t)cyf;

    const float ox = sx - fxf;
    const float oy = sy - fyf;

    const uint32_t base = l * TABLE_SIZE;
    const uint32_t hyc  = cy * HASH_PRIME;
    const uint32_t hyf  = fy * HASH_PRIME;

    // v0=(cx,cy) v1=(cx,fy) v2=(fx,cy) v3=(fx,fy)
    const uint32_t h0 = ((cx ^ hyc) & (TABLE_SIZE - 1u)) + base;
    const uint32_t h1 = ((cx ^ hyf) & (TABLE_SIZE - 1u)) + base;
    const uint32_t h2 = ((fx ^ hyc) & (TABLE_SIZE - 1u)) + base;
    const uint32_t h3 = ((fx ^ hyf) & (TABLE_SIZE - 1u)) + base;

    // 4 independent 8B gathers -> MLP=4 per thread
    const float2 f0 = __ldg(&table[h0]);
    const float2 f1 = __ldg(&table[h1]);
    const float2 f2 = __ldg(&table[h2]);
    const float2 f3 = __ldg(&table[h3]);

    const float omx = 1.0f - ox;
    const float omy = 1.0f - oy;

    float2 e;
    {
        const float f03x = f0.x * ox + f3.x * omx;
        const float f12x = f1.x * ox + f2.x * omx;
        e.x = f03x * oy + f12x * omy;
        const float f03y = f0.y * ox + f3.y * omx;
        const float f12y = f1.y * ox + f2.y * omx;
        e.y = f03y * oy + f12y * omy;
    }

    // out layout: [p][l][2] floats == float2 index p*16 + l == t. Fully coalesced.
    out[t] = e;
}

extern "C" void kernel_launch(void* const* d_in, const int* in_sizes, int n_in,
                              void* d_out, int out_size)
{
    const float2* x     = (const float2*)d_in[0];   // (N_POINTS, 2) float32
    const float2* table = (const float2*)d_in[1];   // (TABLE_SIZE*NUM_LEVELS, 2) float32
    float2* out = (float2*)d_out;                   // (N_POINTS, 32) float32

    const uint32_t total = N_POINTS * NUM_LEVELS;   // 16M threads
    const uint32_t block = 256;
    const uint32_t grid  = (total + block - 1) / block;

    hash_encode_kernel<<<grid, block>>>(x, table, out);
}